// round 5
// baseline (speedup 1.0000x reference)
#include <cuda_runtime.h>
#include <math_constants.h>

// Problem constants (fixed by setup_inputs)
#define CCH   512                 // feature channels
#define KCLS  150                 // classes
#define NPIX  (512 * 512)         // pixels
#define KPAD  160                 // classes padded to multiple of 16 (10 rows/thread * 16)
#define NT    128                 // channel tile per block
#define PCHUNKS 128               // split-K chunks over pixels
#define CHUNK  (NPIX / PCHUNKS)   // 2048 pixels per chunk
#define TP     32                 // pixels per smem tile

// Scratch (allocation-free rule: __device__ globals)
__device__ float g_u[(size_t)KCLS * NPIX];               // exp(logit - max), 157 MB
__device__ float g_w[NPIX];                              // 1 / (per-pixel softmax denom)
__device__ float g_S[KCLS];                              // per-class column sum of probs
__device__ float g_part[(size_t)PCHUNKS * KPAD * CCH];   // split-K partials, 41.9 MB

// ---------------------------------------------------------------------------
// Kernel 1: per-pixel softmax numerator + inverse denominator.
// One thread per pixel. Reads of logits[k*N + n] are coalesced across threads.
// ---------------------------------------------------------------------------
__global__ void softmax_kernel(const float* __restrict__ logits) {
    int n = blockIdx.x * blockDim.x + threadIdx.x;
    if (n >= NPIX) return;

    float m = -CUDART_INF_F;
    for (int k = 0; k < KCLS; k++)
        m = fmaxf(m, logits[(size_t)k * NPIX + n]);

    float s = 0.f;
    for (int k = 0; k < KCLS; k++) {
        float e = __expf(logits[(size_t)k * NPIX + n] - m);
        s += e;
        g_u[(size_t)k * NPIX + n] = e;
    }
    g_w[n] = 1.0f / s;
}

// ---------------------------------------------------------------------------
// Kernel 2: S[k] = sum_n u[k,n] * w[n].  One block per class (150 blocks on
// 148 SMs). Coalesced row reads; deterministic block reduction.
// ---------------------------------------------------------------------------
__global__ void colsum_kernel() {
    __shared__ float red[256];
    int k = blockIdx.x;
    const float* __restrict__ row = g_u + (size_t)k * NPIX;

    float s = 0.f;
    for (int n = threadIdx.x; n < NPIX; n += 256)
        s += row[n] * g_w[n];

    red[threadIdx.x] = s;
    __syncthreads();
    for (int st = 128; st > 0; st >>= 1) {
        if (threadIdx.x < st) red[threadIdx.x] += red[threadIdx.x + st];
        __syncthreads();
    }
    if (threadIdx.x == 0) g_S[k] = red[0];
}

// ---------------------------------------------------------------------------
// Kernel 3: split-K GEMM partials.
//   part[pc][k][c] = sum_{n in chunk pc} (u[k,n]*w[n]) * feats[c,n]
// Block tile: 160 (padded classes) x 128 (channels), K-chunk = 2048 pixels.
// 256 threads, register tile 10x8 (80 accumulators per thread).
// Grid: (PCHUNKS=128, C/NT=4) = 512 blocks.
// ---------------------------------------------------------------------------
__global__ void __launch_bounds__(256, 2) gemm_partial(const float* __restrict__ feats) {
    // Transposed smem tiles: [pixel][row], padded for conflict-free access.
    __shared__ float ps[TP][161];  // probs tile  (161: stride%32==1, conflict-free stores)
    __shared__ float fs[TP][132];  // feats tile  (132: 16B-aligned rows for float4 reads)

    const int pc    = blockIdx.x;
    const int c0blk = blockIdx.y * NT;
    const int n0base = pc * CHUNK;

    const int tid = threadIdx.x;
    const int tx = tid & 15;       // channel group  -> c in [tx*8, tx*8+8)
    const int ty = tid >> 4;       // class group    -> k in [ty*10, ty*10+10)

    const int lp   = tid & 31;     // pixel lane for loading
    const int lrow = tid >> 5;     // 0..7

    float acc[10][8];
#pragma unroll
    for (int i = 0; i < 10; i++)
#pragma unroll
        for (int j = 0; j < 8; j++) acc[i][j] = 0.f;

    for (int t = 0; t < CHUNK / TP; t++) {
        const int n0 = n0base + t * TP;
        const float wv = g_w[n0 + lp];   // per-pixel 1/denominator

        __syncthreads();  // previous compute done before overwriting tiles

        // Load probs tile: 160 rows x 32 px; fold in softmax normalization.
#pragma unroll
        for (int i = 0; i < 20; i++) {
            int k = lrow + i * 8;
            float v = (k < KCLS) ? g_u[(size_t)k * NPIX + n0 + lp] * wv : 0.f;
            ps[lp][k] = v;
        }
        // Load feats tile: 128 rows x 32 px.
#pragma unroll
        for (int i = 0; i < 16; i++) {
            int c = lrow + i * 8;
            fs[lp][c] = feats[(size_t)(c0blk + c) * NPIX + n0 + lp];
        }
        __syncthreads();

        // Outer-product accumulation over the 32 pixels of the tile.
#pragma unroll 4
        for (int p = 0; p < TP; p++) {
            float a[10];
#pragma unroll
            for (int i = 0; i < 10; i++) a[i] = ps[p][ty * 10 + i];

            float4 b0 = *(const float4*)&fs[p][tx * 8];
            float4 b1 = *(const float4*)&fs[p][tx * 8 + 4];
            float b[8] = {b0.x, b0.y, b0.z, b0.w, b1.x, b1.y, b1.z, b1.w};

#pragma unroll
            for (int i = 0; i < 10; i++)
#pragma unroll
                for (int j = 0; j < 8; j++)
                    acc[i][j] = fmaf(a[i], b[j], acc[i][j]);
        }
    }

    // Write this chunk's partial tile (deterministic; no atomics).
    float* out = g_part + (size_t)pc * KPAD * CCH + c0blk;
#pragma unroll
    for (int i = 0; i < 10; i++) {
        int k = ty * 10 + i;
#pragma unroll
        for (int j = 0; j < 8; j++)
            out[(size_t)k * CCH + tx * 8 + j] = acc[i][j];
    }
}

// ---------------------------------------------------------------------------
// Kernel 4: reduce split-K partials and divide by clipped column sum.
// ---------------------------------------------------------------------------
__global__ void finalize_kernel(float* __restrict__ out) {
    int idx = blockIdx.x * 256 + threadIdx.x;  // over KCLS*CCH = 76800
    if (idx >= KCLS * CCH) return;
    int k = idx / CCH;
    int c = idx - k * CCH;

    float s = 0.f;
#pragma unroll 8
    for (int pc = 0; pc < PCHUNKS; pc++)
        s += g_part[(size_t)pc * KPAD * CCH + (size_t)k * CCH + c];

    out[idx] = s / fmaxf(g_S[k], 1e-6f);
}

// ---------------------------------------------------------------------------
extern "C" void kernel_launch(void* const* d_in, const int* in_sizes, int n_in,
                              void* d_out, int out_size) {
    const float* feats  = (const float*)d_in[0];  // (512, 512, 512)
    const float* logits = (const float*)d_in[1];  // (150, 512, 512)
    float* out = (float*)d_out;                   // (150, 512)

    softmax_kernel<<<NPIX / 256, 256>>>(logits);
    colsum_kernel<<<KCLS, 256>>>();
    dim3 grid(PCHUNKS, CCH / NT);
    gemm_partial<<<grid, 256>>>(feats);
    finalize_kernel<<<(KCLS * CCH + 255) / 256, 256>>>(out);
}

// round 6
// speedup vs baseline: 2.0606x; 2.0606x over previous
#include <cuda_runtime.h>
#include <math_constants.h>
#include <cstdint>

// Problem constants (fixed by setup_inputs)
#define CCH   512                 // feature channels
#define KCLS  150                 // classes
#define NPIX  (512 * 512)         // pixels
#define KPAD  160                 // classes padded to multiple of 16
#define NT    128                 // channel tile per block
#define PCHUNKS 128               // split-K chunks over pixels
#define CHUNK  (NPIX / PCHUNKS)   // 2048 pixels per chunk
#define TP     32                 // pixels per smem tile (4 k8 MMA steps)
#define PITCH  36                 // smem row pitch (36 mod 32 = 4 -> conflict-free frag loads)

// Scratch (allocation-free rule: __device__ globals)
__device__ float g_u[(size_t)KCLS * NPIX];               // exp(logit - max), 157 MB
__device__ float g_w[NPIX];                              // 1 / (per-pixel softmax denom)
__device__ float g_S[KCLS];                              // per-class column sum of probs
__device__ float g_part[(size_t)PCHUNKS * KPAD * CCH];   // split-K partials, 41.9 MB

// ---------------------------------------------------------------------------
// Kernel 1: per-pixel softmax numerator + inverse denominator.
// ---------------------------------------------------------------------------
__global__ void softmax_kernel(const float* __restrict__ logits) {
    int n = blockIdx.x * blockDim.x + threadIdx.x;
    if (n >= NPIX) return;

    float m = -CUDART_INF_F;
    for (int k = 0; k < KCLS; k++)
        m = fmaxf(m, logits[(size_t)k * NPIX + n]);

    float s = 0.f;
    for (int k = 0; k < KCLS; k++) {
        float e = __expf(logits[(size_t)k * NPIX + n] - m);
        s += e;
        g_u[(size_t)k * NPIX + n] = e;
    }
    g_w[n] = 1.0f / s;
}

// ---------------------------------------------------------------------------
// Kernel 2: S[k] = sum_n u[k,n] * w[n]. One block per class.
// ---------------------------------------------------------------------------
__global__ void colsum_kernel() {
    __shared__ float red[256];
    int k = blockIdx.x;
    const float* __restrict__ row = g_u + (size_t)k * NPIX;

    float s = 0.f;
    for (int n = threadIdx.x; n < NPIX; n += 256)
        s += row[n] * g_w[n];

    red[threadIdx.x] = s;
    __syncthreads();
    for (int st = 128; st > 0; st >>= 1) {
        if (threadIdx.x < st) red[threadIdx.x] += red[threadIdx.x + st];
        __syncthreads();
    }
    if (threadIdx.x == 0) g_S[k] = red[0];
}

// ---------------------------------------------------------------------------
// TF32 conversion (round-to-nearest; input stays in a b32 register)
// ---------------------------------------------------------------------------
__device__ __forceinline__ uint32_t f2tf(float x) {
    uint32_t u;
    asm("cvt.rna.tf32.f32 %0, %1;" : "=r"(u) : "f"(x));
    return u;
}

// ---------------------------------------------------------------------------
// Kernel 3: split-K GEMM partials on tensor cores (tf32 mma.sync).
//   part[pc][k][c] = sum_{n in chunk pc} (u[k,n]*w[n]) * feats[c,n]
// Block tile 160x128, 8 warps in 2(M) x 4(N): warp tile 80x32.
// Per 8-pixel k-step: 5 m-tiles x 4 n-tiles = 20x mma.m16n8k8.tf32.
// ---------------------------------------------------------------------------
__global__ void __launch_bounds__(256, 2) gemm_partial(const float* __restrict__ feats) {
    __shared__ uint32_t ps[KPAD][PITCH];  // probs  [class][pixel], tf32 bits
    __shared__ uint32_t fs[NT][PITCH];    // feats  [chan ][pixel], tf32 bits

    const int pc     = blockIdx.x;
    const int c0blk  = blockIdx.y * NT;
    const int n0base = pc * CHUNK;

    const int tid   = threadIdx.x;
    const int lane  = tid & 31;
    const int wid   = tid >> 5;
    const int warpM = wid >> 2;    // 0..1  -> class rows [warpM*80, +80)
    const int warpN = wid & 3;     // 0..3  -> channels   [warpN*32, +32)
    const int g     = lane >> 2;   // groupID (mma row / B col)
    const int t4    = lane & 3;    // thread-in-group (mma k col)

    const int lp   = tid & 31;     // pixel lane for cooperative loads
    const int lrow = tid >> 5;     // 0..7

    float acc[5][4][4];
#pragma unroll
    for (int mt = 0; mt < 5; mt++)
#pragma unroll
        for (int nt = 0; nt < 4; nt++)
#pragma unroll
            for (int r = 0; r < 4; r++) acc[mt][nt][r] = 0.f;

    for (int t = 0; t < CHUNK / TP; t++) {
        const int n0 = n0base + t * TP;
        const float wv = g_w[n0 + lp];

        __syncthreads();  // previous step's frag loads done before overwrite

        // probs tile: 160 rows x 32 px, normalization folded in, tf32-rounded
#pragma unroll
        for (int i = 0; i < 20; i++) {
            int k = lrow + i * 8;
            float v = (k < KCLS) ? g_u[(size_t)k * NPIX + n0 + lp] * wv : 0.f;
            ps[k][lp] = f2tf(v);
        }
        // feats tile: 128 rows x 32 px
#pragma unroll
        for (int i = 0; i < 16; i++) {
            int c = lrow + i * 8;
            fs[c][lp] = f2tf(feats[(size_t)(c0blk + c) * NPIX + n0 + lp]);
        }
        __syncthreads();

        // 4 k-steps of 8 pixels each
#pragma unroll
        for (int ks = 0; ks < TP / 8; ks++) {
            const int kk = ks * 8;

            // B fragments (reused across all 5 m-tiles)
            uint32_t b[4][2];
            const uint32_t* pB = &fs[warpN * 32 + g][kk + t4];
#pragma unroll
            for (int nt = 0; nt < 4; nt++) {
                b[nt][0] = pB[(nt * 8) * PITCH];
                b[nt][1] = pB[(nt * 8) * PITCH + 4];
            }

            const uint32_t* pA = &ps[warpM * 80 + g][kk + t4];
#pragma unroll
            for (int mt = 0; mt < 5; mt++) {
                uint32_t a0 = pA[(mt * 16) * PITCH];
                uint32_t a1 = pA[(mt * 16 + 8) * PITCH];
                uint32_t a2 = pA[(mt * 16) * PITCH + 4];
                uint32_t a3 = pA[(mt * 16 + 8) * PITCH + 4];
#pragma unroll
                for (int nt = 0; nt < 4; nt++) {
                    float* d = acc[mt][nt];
                    asm volatile(
                        "mma.sync.aligned.m16n8k8.row.col.f32.tf32.tf32.f32 "
                        "{%0,%1,%2,%3}, {%4,%5,%6,%7}, {%8,%9}, {%0,%1,%2,%3};"
                        : "+f"(d[0]), "+f"(d[1]), "+f"(d[2]), "+f"(d[3])
                        : "r"(a0), "r"(a1), "r"(a2), "r"(a3),
                          "r"(b[nt][0]), "r"(b[nt][1]));
                }
            }
        }
    }

    // Write this chunk's partial tile (deterministic; no atomics).
    // D fragment layout: d0=(g, 2*t4) d1=(g, 2*t4+1) d2=(g+8, 2*t4) d3=(g+8, 2*t4+1)
    float* out = g_part + (size_t)pc * KPAD * CCH + c0blk;
#pragma unroll
    for (int mt = 0; mt < 5; mt++) {
        int row = warpM * 80 + mt * 16 + g;
#pragma unroll
        for (int nt = 0; nt < 4; nt++) {
            int col = warpN * 32 + nt * 8 + 2 * t4;
            *(float2*)&out[(size_t)row * CCH + col] =
                make_float2(acc[mt][nt][0], acc[mt][nt][1]);
            *(float2*)&out[(size_t)(row + 8) * CCH + col] =
                make_float2(acc[mt][nt][2], acc[mt][nt][3]);
        }
    }
}

// ---------------------------------------------------------------------------
// Kernel 4: reduce split-K partials and divide by clipped column sum.
// ---------------------------------------------------------------------------
__global__ void finalize_kernel(float* __restrict__ out) {
    int idx = blockIdx.x * 256 + threadIdx.x;  // over KCLS*CCH = 76800
    if (idx >= KCLS * CCH) return;
    int k = idx / CCH;
    int c = idx - k * CCH;

    float s = 0.f;
#pragma unroll 8
    for (int pc = 0; pc < PCHUNKS; pc++)
        s += g_part[(size_t)pc * KPAD * CCH + (size_t)k * CCH + c];

    out[idx] = s / fmaxf(g_S[k], 1e-6f);
}

// ---------------------------------------------------------------------------
extern "C" void kernel_launch(void* const* d_in, const int* in_sizes, int n_in,
                              void* d_out, int out_size) {
    const float* feats  = (const float*)d_in[0];  // (512, 512, 512)
    const float* logits = (const float*)d_in[1];  // (150, 512, 512)
    float* out = (float*)d_out;                   // (150, 512)

    softmax_kernel<<<NPIX / 256, 256>>>(logits);
    colsum_kernel<<<KCLS, 256>>>();
    dim3 grid(PCHUNKS, CCH / NT);
    gemm_partial<<<grid, 256>>>(feats);
    finalize_kernel<<<(KCLS * CCH + 255) / 256, 256>>>(out);
}

// round 9
// speedup vs baseline: 3.1562x; 1.5317x over previous
#include <cuda_runtime.h>
#include <math_constants.h>
#include <cstdint>

// Problem constants (fixed by setup_inputs)
#define CCH   512                 // feature channels
#define KCLS  150                 // classes
#define NPIX  (512 * 512)         // pixels
#define KPAD  160                 // classes padded to multiple of 16
#define NT    128                 // channel tile per block
#define PCHUNKS 64                // split-K chunks over pixels (grid 256 = 1 wave @ occ2)
#define CHUNK  (NPIX / PCHUNKS)   // 4096 pixels per chunk
#define TP     32                 // pixels per smem tile (4 k8 MMA steps)
#define PITCH  36                 // smem row pitch in words (36%32=4 -> conflict-free frags,
                                  //  144B rows -> 16B-aligned for cp.async)
#define ITERS  (CHUNK / TP)       // 128
#define PS_WORDS (KPAD * PITCH)   // 5760
#define FS_WORDS (NT * PITCH)     // 4608
#define BUF_WORDS (PS_WORDS + FS_WORDS)  // 10368 (multiple of 32 -> bank math invariant)

// Scratch (allocation-free rule: __device__ globals)
__device__ float g_u[(size_t)KCLS * NPIX];               // normalized probs, tf32 bits, 157 MB
__device__ float g_S[KCLS];                              // per-class column sum of probs
__device__ float g_part[(size_t)PCHUNKS * KPAD * CCH];   // split-K partials, 21 MB

// ---------------------------------------------------------------------------
// TF32 conversion (round-to-nearest)
// ---------------------------------------------------------------------------
__device__ __forceinline__ uint32_t f2tf(float x) {
    uint32_t u;
    asm("cvt.rna.tf32.f32 %0, %1;" : "=r"(u) : "f"(x));
    return u;
}

// ---------------------------------------------------------------------------
// Kernel 1: online softmax, writes fully normalized probs as tf32 bits.
// Pass 1: online max+sum (1 read). Pass 2: recompute exp, scale, store (1 read
// + 1 write). GEMM then needs NO per-pixel weight and NO conversion.
// ---------------------------------------------------------------------------
__global__ void softmax_kernel(const float* __restrict__ logits) {
    int n = blockIdx.x * blockDim.x + threadIdx.x;
    if (n >= NPIX) return;

    float m = -CUDART_INF_F, s = 0.f;
#pragma unroll 5
    for (int k = 0; k < KCLS; k++) {
        float x = logits[(size_t)k * NPIX + n];
        float m2 = fmaxf(m, x);
        s = s * __expf(m - m2) + __expf(x - m2);   // exp(-inf)=0 handles first iter
        m = m2;
    }
    float winv = 1.0f / s;

#pragma unroll 5
    for (int k = 0; k < KCLS; k++) {
        float e = __expf(logits[(size_t)k * NPIX + n] - m) * winv;
        ((uint32_t*)g_u)[(size_t)k * NPIX + n] = f2tf(e);
    }
}

// ---------------------------------------------------------------------------
// Kernel 2: S[k] = sum_n probs[k,n]. One block per class. (tf32 bits are
// valid fp32 values, just with low mantissa bits zeroed.)
// ---------------------------------------------------------------------------
__global__ void colsum_kernel() {
    __shared__ float red[256];
    int k = blockIdx.x;
    const float* __restrict__ row = g_u + (size_t)k * NPIX;

    float s = 0.f;
    for (int n = threadIdx.x; n < NPIX; n += 256)
        s += row[n];

    red[threadIdx.x] = s;
    __syncthreads();
    for (int st = 128; st > 0; st >>= 1) {
        if (threadIdx.x < st) red[threadIdx.x] += red[threadIdx.x + st];
        __syncthreads();
    }
    if (threadIdx.x == 0) g_S[k] = red[0];
}

// ---------------------------------------------------------------------------
// cp.async helpers
// ---------------------------------------------------------------------------
__device__ __forceinline__ void cpa16(uint32_t smem_addr, const void* gptr) {
    asm volatile("cp.async.cg.shared.global [%0], [%1], 16;"
                 :: "r"(smem_addr), "l"(gptr));
}
__device__ __forceinline__ void cpa_commit() {
    asm volatile("cp.async.commit_group;");
}

// ---------------------------------------------------------------------------
// Kernel 3: split-K GEMM partials, tf32 mma.sync, cp.async double-buffered.
//   part[pc][k][c] = sum_{n in chunk pc} probs[k,n] * feats[c,n]
// Block tile 160x128, 8 warps 2(M)x4(N), warp tile 80x32.
// Mainloop: prefetch tile t+1 (cp.async) while computing tile t (MMA).
// Feats enter the MMA as raw fp32 bits (HW uses tf32 field => RZ truncation).
// ---------------------------------------------------------------------------
__global__ void __launch_bounds__(256, 2) gemm_partial(const float* __restrict__ feats) {
    extern __shared__ uint32_t smem[];  // 2 buffers: [ps(160x36) | fs(128x36)]

    const int pc     = blockIdx.x;
    const int c0blk  = blockIdx.y * NT;
    const int n0base = pc * CHUNK;

    const int tid   = threadIdx.x;
    const int lane  = tid & 31;
    const int wid   = tid >> 5;
    const int warpM = wid >> 2;    // 0..1 -> class rows [warpM*80, +80)
    const int warpN = wid & 3;     // 0..3 -> channels   [warpN*32, +32)
    const int g     = lane >> 2;   // mma group row
    const int t4    = lane & 3;    // mma k col

    const uint32_t smem_u32 = (uint32_t)__cvta_generic_to_shared(smem);

    // Zero padding rows 150..159 of BOTH probs buffers once (never overwritten:
    // cp.async only touches rows < 150, so the zeros persist for every tile).
    for (int i = tid; i < 2 * 10 * PITCH; i += 256) {
        int b = i / (10 * PITCH), w = i % (10 * PITCH);
        smem[b * BUF_WORDS + KCLS * PITCH + w] = 0;
    }

    float acc[5][4][4];
#pragma unroll
    for (int mt = 0; mt < 5; mt++)
#pragma unroll
        for (int nt = 0; nt < 4; nt++)
#pragma unroll
            for (int r = 0; r < 4; r++) acc[mt][nt][r] = 0.f;

    // ---- async tile issue: 150x32 probs + 128x32 feats, 16B chunks ----
    auto issue = [&](int t, int buf) {
        const int n0 = n0base + t * TP;
        const uint32_t ps_b = smem_u32 + buf * BUF_WORDS * 4;
        const uint32_t fs_b = ps_b + PS_WORDS * 4;
        // probs: 150 rows x 8 chunks = 1200
        for (int c = tid; c < KCLS * 8; c += 256) {
            int row = c >> 3, col = (c & 7) * 4;
            cpa16(ps_b + (row * PITCH + col) * 4,
                  g_u + (size_t)row * NPIX + n0 + col);
        }
        // feats: 128 rows x 8 chunks = 1024
        for (int c = tid; c < NT * 8; c += 256) {
            int row = c >> 3, col = (c & 7) * 4;
            cpa16(fs_b + (row * PITCH + col) * 4,
                  feats + (size_t)(c0blk + row) * NPIX + n0 + col);
        }
        cpa_commit();
    };

    issue(0, 0);

    for (int t = 0; t < ITERS; t++) {
        const int cur = t & 1;
        if (t + 1 < ITERS) {
            issue(t + 1, cur ^ 1);
            asm volatile("cp.async.wait_group 1;");
        } else {
            asm volatile("cp.async.wait_group 0;");
        }
        __syncthreads();   // tile t visible to all warps

        const uint32_t* ps = smem + cur * BUF_WORDS;
        const uint32_t* fs = ps + PS_WORDS;

#pragma unroll
        for (int ks = 0; ks < TP / 8; ks++) {
            const int kk = ks * 8;

            uint32_t b[4][2];
            const uint32_t* pB = &fs[(warpN * 32 + g) * PITCH + kk + t4];
#pragma unroll
            for (int nt = 0; nt < 4; nt++) {
                b[nt][0] = pB[(nt * 8) * PITCH];
                b[nt][1] = pB[(nt * 8) * PITCH + 4];
            }

            const uint32_t* pA = &ps[(warpM * 80 + g) * PITCH + kk + t4];
#pragma unroll
            for (int mt = 0; mt < 5; mt++) {
                uint32_t a0 = pA[(mt * 16) * PITCH];
                uint32_t a1 = pA[(mt * 16 + 8) * PITCH];
                uint32_t a2 = pA[(mt * 16) * PITCH + 4];
                uint32_t a3 = pA[(mt * 16 + 8) * PITCH + 4];
#pragma unroll
                for (int nt = 0; nt < 4; nt++) {
                    float* d = acc[mt][nt];
                    asm volatile(
                        "mma.sync.aligned.m16n8k8.row.col.f32.tf32.tf32.f32 "
                        "{%0,%1,%2,%3}, {%4,%5,%6,%7}, {%8,%9}, {%0,%1,%2,%3};"
                        : "+f"(d[0]), "+f"(d[1]), "+f"(d[2]), "+f"(d[3])
                        : "r"(a0), "r"(a1), "r"(a2), "r"(a3),
                          "r"(b[nt][0]), "r"(b[nt][1]));
                }
            }
        }
        __syncthreads();   // all warps done with buffer `cur` before it is refilled
    }

    // Write this chunk's partial tile (deterministic; no atomics).
    float* out = g_part + (size_t)pc * KPAD * CCH + c0blk;
#pragma unroll
    for (int mt = 0; mt < 5; mt++) {
        int row = warpM * 80 + mt * 16 + g;
#pragma unroll
        for (int nt = 0; nt < 4; nt++) {
            int col = warpN * 32 + nt * 8 + 2 * t4;
            *(float2*)&out[(size_t)row * CCH + col] =
                make_float2(acc[mt][nt][0], acc[mt][nt][1]);
            *(float2*)&out[(size_t)(row + 8) * CCH + col] =
                make_float2(acc[mt][nt][2], acc[mt][nt][3]);
        }
    }
}

// ---------------------------------------------------------------------------
// Kernel 4: reduce split-K partials and divide by clipped column sum.
// ---------------------------------------------------------------------------
__global__ void finalize_kernel(float* __restrict__ out) {
    int idx = blockIdx.x * 256 + threadIdx.x;  // over KCLS*CCH = 76800
    if (idx >= KCLS * CCH) return;
    int k = idx / CCH;
    int c = idx - k * CCH;

    float s = 0.f;
#pragma unroll 8
    for (int pc = 0; pc < PCHUNKS; pc++)
        s += g_part[(size_t)pc * KPAD * CCH + (size_t)k * CCH + c];

    out[idx] = s / fmaxf(g_S[k], 1e-6f);
}

// ---------------------------------------------------------------------------
extern "C" void kernel_launch(void* const* d_in, const int* in_sizes, int n_in,
                              void* d_out, int out_size) {
    const float* feats  = (const float*)d_in[0];  // (512, 512, 512)
    const float* logits = (const float*)d_in[1];  // (150, 512, 512)
    float* out = (float*)d_out;                   // (150, 512)

    const int smem_bytes = 2 * BUF_WORDS * 4;     // 82944
    cudaFuncSetAttribute(gemm_partial,
                         cudaFuncAttributeMaxDynamicSharedMemorySize, smem_bytes);

    softmax_kernel<<<NPIX / 256, 256>>>(logits);
    colsum_kernel<<<KCLS, 256>>>();
    dim3 grid(PCHUNKS, CCH / NT);
    gemm_partial<<<grid, 256, smem_bytes>>>(feats);
    finalize_kernel<<<(KCLS * CCH + 255) / 256, 256>>>(out);
}

// round 12
// speedup vs baseline: 3.6726x; 1.1636x over previous
#include <cuda_runtime.h>
#include <cuda_fp16.h>
#include <math_constants.h>
#include <cstdint>

// Problem constants (fixed by setup_inputs)
#define CCH   512                 // feature channels
#define KCLS  150                 // classes
#define NPIX  (512 * 512)         // pixels
#define KPAD  160                 // classes padded to multiple of 16
#define NT    128                 // channel tile per block
#define PCHUNKS 64                // split-K chunks (grid 256 = 1 wave @ occ2)
#define CHUNK  (NPIX / PCHUNKS)   // 4096 pixels per chunk
#define TP     32                 // pixels per smem tile (4 k8 MMA steps)
#define ITERS  (CHUNK / TP)       // 128
#define NSEG   8                  // colsum pixel segments

// smem probs tile: fp16, pitch 40 halves (80B rows, 16B-aligned, conflict-free)
#define PITCHH 40
#define PS_BYTES (KPAD * PITCHH * 2)      // 12800
// smem feats tile: fp32, pitch 36 words (144B rows)
#define PITCH  36
#define FS_WORDS (NT * PITCH)             // 4608
#define FS_BYTES (FS_WORDS * 4)           // 18432
#define BUF_BYTES (PS_BYTES + FS_BYTES)   // 31232
#define SMEM_TOTAL (2 * BUF_BYTES)        // 62464

// Scratch (allocation-free rule: __device__ globals)
__device__ __half g_u[(size_t)KCLS * NPIX];              // normalized probs, fp16, 79 MB
__device__ float g_Sp[KCLS * NSEG];                      // segmented column sums
__device__ float g_part[(size_t)PCHUNKS * KPAD * CCH];   // split-K partials, 21 MB

// ---------------------------------------------------------------------------
// Kernel 1: online softmax, writes fully normalized probs as fp16.
// fp16 RN quantization (eps 2^-11) == tf32 RNA quantization; exact in tf32.
// ---------------------------------------------------------------------------
__global__ void softmax_kernel(const float* __restrict__ logits) {
    int n = blockIdx.x * blockDim.x + threadIdx.x;
    if (n >= NPIX) return;

    float m = -CUDART_INF_F, s = 0.f;
#pragma unroll 5
    for (int k = 0; k < KCLS; k++) {
        float x = logits[(size_t)k * NPIX + n];
        float m2 = fmaxf(m, x);
        s = s * __expf(m - m2) + __expf(x - m2);
        m = m2;
    }
    float winv = 1.0f / s;

#pragma unroll 5
    for (int k = 0; k < KCLS; k++) {
        float e = __expf(logits[(size_t)k * NPIX + n] - m) * winv;
        g_u[(size_t)k * NPIX + n] = __float2half_rn(e);
    }
}

// ---------------------------------------------------------------------------
// Kernel 2: segmented column sums of fp16 probs. Grid (KCLS, NSEG).
// ---------------------------------------------------------------------------
__global__ void colsum_kernel() {
    __shared__ float red[256];
    const int k = blockIdx.x, seg = blockIdx.y;
    const int len = NPIX / NSEG;
    const __half2* __restrict__ row =
        (const __half2*)(g_u + (size_t)k * NPIX + (size_t)seg * len);

    float s = 0.f;
#pragma unroll 4
    for (int n = threadIdx.x; n < len / 2; n += 256) {
        float2 v = __half22float2(row[n]);
        s += v.x + v.y;
    }

    red[threadIdx.x] = s;
    __syncthreads();
    for (int st = 128; st > 0; st >>= 1) {
        if (threadIdx.x < st) red[threadIdx.x] += red[threadIdx.x + st];
        __syncthreads();
    }
    if (threadIdx.x == 0) g_Sp[k * NSEG + seg] = red[0];
}

// ---------------------------------------------------------------------------
// cp.async helpers
// ---------------------------------------------------------------------------
__device__ __forceinline__ void cpa16(uint32_t smem_addr, const void* gptr) {
    asm volatile("cp.async.cg.shared.global [%0], [%1], 16;"
                 :: "r"(smem_addr), "l"(gptr));
}

// ---------------------------------------------------------------------------
// Kernel 3: split-K GEMM partials, tf32 mma.sync, cp.async double-buffered.
//   part[pc][k][c] = sum_{n in chunk pc} probs[k,n] * feats[c,n]
// Probs live in smem as fp16 (exact in tf32 after cvt); feats as raw fp32
// bits (HW reads the tf32 field => RZ truncation). Block tile 160x128,
// 8 warps 2(M)x4(N), warp tile 80x32.
// ---------------------------------------------------------------------------
__global__ void __launch_bounds__(256, 2) gemm_partial(const float* __restrict__ feats) {
    extern __shared__ uint32_t smem[];  // 2 x [ ps fp16 160x40 | fs fp32 128x36 ]

    const int pc     = blockIdx.x;
    const int c0blk  = blockIdx.y * NT;
    const int n0base = pc * CHUNK;

    const int tid   = threadIdx.x;
    const int lane  = tid & 31;
    const int wid   = tid >> 5;
    const int warpM = wid >> 2;    // 0..1 -> class rows [warpM*80, +80)
    const int warpN = wid & 3;     // 0..3 -> channels   [warpN*32, +32)
    const int g     = lane >> 2;   // mma group row
    const int t4    = lane & 3;    // mma k col

    const uint32_t smem_u32 = (uint32_t)__cvta_generic_to_shared(smem);

    // Zero probs padding rows 150..159 (both buffers) once; cp.async never
    // touches rows >= 150, so the zeros persist for every tile.
    for (int i = tid; i < 2 * 10 * PITCHH / 2; i += 256) {  // 400 words
        int b = i / (10 * PITCHH / 2), w = i % (10 * PITCHH / 2);
        *(uint32_t*)((char*)smem + b * BUF_BYTES + KCLS * PITCHH * 2 + w * 4) = 0;
    }

    float acc[5][4][4];
#pragma unroll
    for (int mt = 0; mt < 5; mt++)
#pragma unroll
        for (int nt = 0; nt < 4; nt++)
#pragma unroll
            for (int r = 0; r < 4; r++) acc[mt][nt][r] = 0.f;

    // ---- async tile issue: probs 150 rows x 4 x 16B; feats 128 rows x 8 x 16B
    auto issue = [&](int t, int buf) {
        const int n0 = n0base + t * TP;
        const uint32_t ps_b = smem_u32 + buf * BUF_BYTES;
        const uint32_t fs_b = ps_b + PS_BYTES;
        for (int c = tid; c < KCLS * 4; c += 256) {          // 600 ops
            int row = c >> 2, ch = c & 3;
            cpa16(ps_b + row * (PITCHH * 2) + ch * 16,
                  g_u + (size_t)row * NPIX + n0 + ch * 8);
        }
        for (int c = tid; c < NT * 8; c += 256) {            // 1024 ops
            int row = c >> 3, ch = c & 7;
            cpa16(fs_b + row * (PITCH * 4) + ch * 16,
                  feats + (size_t)(c0blk + row) * NPIX + n0 + ch * 4);
        }
        asm volatile("cp.async.commit_group;");
    };

    issue(0, 0);

    for (int t = 0; t < ITERS; t++) {
        const int cur = t & 1;
        if (t + 1 < ITERS) {
            issue(t + 1, cur ^ 1);
            asm volatile("cp.async.wait_group 1;");
        } else {
            asm volatile("cp.async.wait_group 0;");
        }
        __syncthreads();   // tile t visible to all warps

        const __half*    ps = (const __half*)((char*)smem + cur * BUF_BYTES);
        const uint32_t*  fs = (const uint32_t*)((char*)smem + cur * BUF_BYTES + PS_BYTES);

#pragma unroll
        for (int ks = 0; ks < TP / 8; ks++) {
            const int kk = ks * 8;

            // B fragments: feats fp32 bits (tf32 RZ in HW)
            uint32_t b[4][2];
            const uint32_t* pB = &fs[(warpN * 32 + g) * PITCH + kk + t4];
#pragma unroll
            for (int nt = 0; nt < 4; nt++) {
                b[nt][0] = pB[(nt * 8) * PITCH];
                b[nt][1] = pB[(nt * 8) * PITCH + 4];
            }

            // A fragments: fp16 -> fp32 (exact) -> tf32 operand
            const __half* pA = &ps[(warpM * 80 + g) * PITCHH + kk + t4];
#pragma unroll
            for (int mt = 0; mt < 5; mt++) {
                uint32_t a0 = __float_as_uint(__half2float(pA[(mt * 16)     * PITCHH]));
                uint32_t a1 = __float_as_uint(__half2float(pA[(mt * 16 + 8) * PITCHH]));
                uint32_t a2 = __float_as_uint(__half2float(pA[(mt * 16)     * PITCHH + 4]));
                uint32_t a3 = __float_as_uint(__half2float(pA[(mt * 16 + 8) * PITCHH + 4]));
#pragma unroll
                for (int nt = 0; nt < 4; nt++) {
                    float* d = acc[mt][nt];
                    asm volatile(
                        "mma.sync.aligned.m16n8k8.row.col.f32.tf32.tf32.f32 "
                        "{%0,%1,%2,%3}, {%4,%5,%6,%7}, {%8,%9}, {%0,%1,%2,%3};"
                        : "+f"(d[0]), "+f"(d[1]), "+f"(d[2]), "+f"(d[3])
                        : "r"(a0), "r"(a1), "r"(a2), "r"(a3),
                          "r"(b[nt][0]), "r"(b[nt][1]));
                }
            }
        }
        __syncthreads();   // all warps done with buffer `cur` before refill
    }

    // Write this chunk's partial tile (deterministic; no atomics).
    float* out = g_part + (size_t)pc * KPAD * CCH + c0blk;
#pragma unroll
    for (int mt = 0; mt < 5; mt++) {
        int row = warpM * 80 + mt * 16 + g;
#pragma unroll
        for (int nt = 0; nt < 4; nt++) {
            int col = warpN * 32 + nt * 8 + 2 * t4;
            *(float2*)&out[(size_t)row * CCH + col] =
                make_float2(acc[mt][nt][0], acc[mt][nt][1]);
            *(float2*)&out[(size_t)(row + 8) * CCH + col] =
                make_float2(acc[mt][nt][2], acc[mt][nt][3]);
        }
    }
}

// ---------------------------------------------------------------------------
// Kernel 4: reduce split-K partials, divide by clipped column sum.
// ---------------------------------------------------------------------------
__global__ void finalize_kernel(float* __restrict__ out) {
    int idx = blockIdx.x * 256 + threadIdx.x;  // over KCLS*CCH = 76800
    if (idx >= KCLS * CCH) return;
    int k = idx / CCH;
    int c = idx - k * CCH;

    float S = 0.f;
#pragma unroll
    for (int s = 0; s < NSEG; s++) S += g_Sp[k * NSEG + s];

    float acc = 0.f;
#pragma unroll 8
    for (int pc = 0; pc < PCHUNKS; pc++)
        acc += g_part[(size_t)pc * KPAD * CCH + (size_t)k * CCH + c];

    out[idx] = acc / fmaxf(S, 1e-6f);
}

// ---------------------------------------------------------------------------
extern "C" void kernel_launch(void* const* d_in, const int* in_sizes, int n_in,
                              void* d_out, int out_size) {
    const float* feats  = (const float*)d_in[0];  // (512, 512, 512)
    const float* logits = (const float*)d_in[1];  // (150, 512, 512)
    float* out = (float*)d_out;                   // (150, 512)

    cudaFuncSetAttribute(gemm_partial,
                         cudaFuncAttributeMaxDynamicSharedMemorySize, SMEM_TOTAL);

    softmax_kernel<<<NPIX / 256, 256>>>(logits);
    colsum_kernel<<<dim3(KCLS, NSEG), 256>>>();
    gemm_partial<<<dim3(PCHUNKS, CCH / NT), 256, SMEM_TOTAL>>>(feats);
    finalize_kernel<<<(KCLS * CCH + 255) / 256, 256>>>(out);
}

// round 13
// speedup vs baseline: 4.5473x; 1.2382x over previous
#include <cuda_runtime.h>
#include <cuda_fp16.h>
#include <math_constants.h>
#include <cstdint>

// Problem constants (fixed by setup_inputs)
#define CCH   512                 // feature channels
#define KCLS  150                 // classes
#define NPIX  (512 * 512)         // pixels
#define KPAD  160                 // classes padded to multiple of 16
#define NT    128                 // channel tile per block
#define PCHUNKS 64                // split-K chunks (grid 256 = 1 wave @ occ2)
#define CHUNK  (NPIX / PCHUNKS)   // 4096 pixels per chunk
#define TP     32                 // pixels per smem tile (2 k16 MMA steps)
#define ITERS  (CHUNK / TP)       // 128
#define NSEG   8                  // colsum pixel segments

// smem probs tile: fp16, pitch 40 halves (80B rows, 16B-aligned, conflict-free)
#define PITCHH 40
#define PS_BYTES (KPAD * PITCHH * 2)      // 12800
// smem feats tile: fp32, pitch 36 words (144B rows)
#define PITCH  36
#define FS_WORDS (NT * PITCH)             // 4608
#define FS_BYTES (FS_WORDS * 4)           // 18432
#define BUF_BYTES (PS_BYTES + FS_BYTES)   // 31232
#define SMEM_TOTAL (2 * BUF_BYTES)        // 62464

// Scratch (allocation-free rule: __device__ globals)
__device__ __half g_u[(size_t)KCLS * NPIX];              // normalized probs, fp16, 79 MB
__device__ float g_Sp[KCLS * NSEG];                      // segmented column sums
__device__ float g_part[(size_t)PCHUNKS * KPAD * CCH];   // split-K partials, 21 MB

// ---------------------------------------------------------------------------
// Kernel 1: online softmax, writes fully normalized probs as fp16.
// ---------------------------------------------------------------------------
__global__ void softmax_kernel(const float* __restrict__ logits) {
    int n = blockIdx.x * blockDim.x + threadIdx.x;
    if (n >= NPIX) return;

    float m = -CUDART_INF_F, s = 0.f;
#pragma unroll 5
    for (int k = 0; k < KCLS; k++) {
        float x = logits[(size_t)k * NPIX + n];
        float m2 = fmaxf(m, x);
        s = s * __expf(m - m2) + __expf(x - m2);
        m = m2;
    }
    float winv = 1.0f / s;

#pragma unroll 5
    for (int k = 0; k < KCLS; k++) {
        float e = __expf(logits[(size_t)k * NPIX + n] - m) * winv;
        g_u[(size_t)k * NPIX + n] = __float2half_rn(e);
    }
}

// ---------------------------------------------------------------------------
// Kernel 2: segmented column sums of fp16 probs. Grid (KCLS, NSEG).
// ---------------------------------------------------------------------------
__global__ void colsum_kernel() {
    __shared__ float red[256];
    const int k = blockIdx.x, seg = blockIdx.y;
    const int len = NPIX / NSEG;
    const __half2* __restrict__ row =
        (const __half2*)(g_u + (size_t)k * NPIX + (size_t)seg * len);

    float s = 0.f;
#pragma unroll 4
    for (int n = threadIdx.x; n < len / 2; n += 256) {
        float2 v = __half22float2(row[n]);
        s += v.x + v.y;
    }

    red[threadIdx.x] = s;
    __syncthreads();
    for (int st = 128; st > 0; st >>= 1) {
        if (threadIdx.x < st) red[threadIdx.x] += red[threadIdx.x + st];
        __syncthreads();
    }
    if (threadIdx.x == 0) g_Sp[k * NSEG + seg] = red[0];
}

// ---------------------------------------------------------------------------
// helpers
// ---------------------------------------------------------------------------
__device__ __forceinline__ void cpa16(uint32_t smem_addr, const void* gptr) {
    asm volatile("cp.async.cg.shared.global [%0], [%1], 16;"
                 :: "r"(smem_addr), "l"(gptr));
}
// pack (lo=k_even, hi=k_odd) floats into one f16x2 register
__device__ __forceinline__ uint32_t f22h(float2 v) {
    uint32_t r;
    asm("cvt.rn.f16x2.f32 %0, %1, %2;" : "=r"(r) : "f"(v.y), "f"(v.x));
    return r;
}

// ---------------------------------------------------------------------------
// Kernel 3: split-K GEMM partials, fp16 mma.m16n8k16 (fp32 accum),
// cp.async double-buffered.
//   part[pc][k][c] = sum_{n in chunk pc} probs[k,n] * feats[c,n]
// A = probs (fp16 smem, direct b32 pair loads); B = feats (fp32 smem,
// packed to f16x2 in registers). Block tile 160x128, 8 warps 2(M)x4(N),
// warp tile 80x32. Per 32-px tile: 2 k16 steps x 20 mma = 40 HMMA.
// ---------------------------------------------------------------------------
__global__ void __launch_bounds__(256, 2) gemm_partial(const float* __restrict__ feats) {
    extern __shared__ uint32_t smem[];  // 2 x [ ps fp16 160x40 | fs fp32 128x36 ]

    const int pc     = blockIdx.x;
    const int c0blk  = blockIdx.y * NT;
    const int n0base = pc * CHUNK;

    const int tid   = threadIdx.x;
    const int lane  = tid & 31;
    const int wid   = tid >> 5;
    const int warpM = wid >> 2;    // 0..1 -> class rows [warpM*80, +80)
    const int warpN = wid & 3;     // 0..3 -> channels   [warpN*32, +32)
    const int g     = lane >> 2;   // mma group row
    const int t4    = lane & 3;    // mma k quad

    const uint32_t smem_u32 = (uint32_t)__cvta_generic_to_shared(smem);

    // Zero probs padding rows 150..159 (both buffers) once; cp.async never
    // touches rows >= 150, so the zeros persist for every tile.
    for (int i = tid; i < 2 * 10 * PITCHH / 2; i += 256) {  // 400 words
        int b = i / (10 * PITCHH / 2), w = i % (10 * PITCHH / 2);
        *(uint32_t*)((char*)smem + b * BUF_BYTES + KCLS * PITCHH * 2 + w * 4) = 0;
    }

    float acc[5][4][4];
#pragma unroll
    for (int mt = 0; mt < 5; mt++)
#pragma unroll
        for (int nt = 0; nt < 4; nt++)
#pragma unroll
            for (int r = 0; r < 4; r++) acc[mt][nt][r] = 0.f;

    // ---- async tile issue: probs 150 rows x 4 x 16B; feats 128 rows x 8 x 16B
    auto issue = [&](int t, int buf) {
        const int n0 = n0base + t * TP;
        const uint32_t ps_b = smem_u32 + buf * BUF_BYTES;
        const uint32_t fs_b = ps_b + PS_BYTES;
        for (int c = tid; c < KCLS * 4; c += 256) {          // 600 ops
            int row = c >> 2, ch = c & 3;
            cpa16(ps_b + row * (PITCHH * 2) + ch * 16,
                  g_u + (size_t)row * NPIX + n0 + ch * 8);
        }
        for (int c = tid; c < NT * 8; c += 256) {            // 1024 ops
            int row = c >> 3, ch = c & 7;
            cpa16(fs_b + row * (PITCH * 4) + ch * 16,
                  feats + (size_t)(c0blk + row) * NPIX + n0 + ch * 4);
        }
        asm volatile("cp.async.commit_group;");
    };

    issue(0, 0);

    for (int t = 0; t < ITERS; t++) {
        const int cur = t & 1;
        if (t + 1 < ITERS) {
            issue(t + 1, cur ^ 1);
            asm volatile("cp.async.wait_group 1;");
        } else {
            asm volatile("cp.async.wait_group 0;");
        }
        __syncthreads();   // tile t visible to all warps

        const __half* ps = (const __half*)((char*)smem + cur * BUF_BYTES);
        const float*  fs = (const float*)((char*)smem + cur * BUF_BYTES + PS_BYTES);

#pragma unroll
        for (int ks = 0; ks < TP / 16; ks++) {
            const int kk = ks * 16;

            // B fragments: feats fp32 -> f16x2 packs
            // b0 = col g, k = kk+2t4,+1 ; b1 = k = kk+8+2t4,+1
            uint32_t b[4][2];
            const float* pB = &fs[(warpN * 32 + g) * PITCH + kk + 2 * t4];
#pragma unroll
            for (int nt = 0; nt < 4; nt++) {
                b[nt][0] = f22h(*(const float2*)&pB[(nt * 8) * PITCH]);
                b[nt][1] = f22h(*(const float2*)&pB[(nt * 8) * PITCH + 8]);
            }

            // A fragments: fp16 pairs straight from smem
            // a0=(row g, k kk+2t4..+1) a1=(row g+8) a2=(row g, k+8) a3=(row g+8, k+8)
            const __half* pA = &ps[(warpM * 80 + g) * PITCHH + kk + 2 * t4];
#pragma unroll
            for (int mt = 0; mt < 5; mt++) {
                uint32_t a0 = *(const uint32_t*)&pA[(mt * 16)     * PITCHH];
                uint32_t a1 = *(const uint32_t*)&pA[(mt * 16 + 8) * PITCHH];
                uint32_t a2 = *(const uint32_t*)&pA[(mt * 16)     * PITCHH + 8];
                uint32_t a3 = *(const uint32_t*)&pA[(mt * 16 + 8) * PITCHH + 8];
#pragma unroll
                for (int nt = 0; nt < 4; nt++) {
                    float* d = acc[mt][nt];
                    asm volatile(
                        "mma.sync.aligned.m16n8k16.row.col.f32.f16.f16.f32 "
                        "{%0,%1,%2,%3}, {%4,%5,%6,%7}, {%8,%9}, {%0,%1,%2,%3};"
                        : "+f"(d[0]), "+f"(d[1]), "+f"(d[2]), "+f"(d[3])
                        : "r"(a0), "r"(a1), "r"(a2), "r"(a3),
                          "r"(b[nt][0]), "r"(b[nt][1]));
                }
            }
        }
        __syncthreads();   // all warps done with buffer `cur` before refill
    }

    // Write this chunk's partial tile (deterministic; no atomics).
    float* out = g_part + (size_t)pc * KPAD * CCH + c0blk;
#pragma unroll
    for (int mt = 0; mt < 5; mt++) {
        int row = warpM * 80 + mt * 16 + g;
#pragma unroll
        for (int nt = 0; nt < 4; nt++) {
            int col = warpN * 32 + nt * 8 + 2 * t4;
            *(float2*)&out[(size_t)row * CCH + col] =
                make_float2(acc[mt][nt][0], acc[mt][nt][1]);
            *(float2*)&out[(size_t)(row + 8) * CCH + col] =
                make_float2(acc[mt][nt][2], acc[mt][nt][3]);
        }
    }
}

// ---------------------------------------------------------------------------
// Kernel 4: reduce split-K partials, divide by clipped column sum.
// ---------------------------------------------------------------------------
__global__ void finalize_kernel(float* __restrict__ out) {
    int idx = blockIdx.x * 256 + threadIdx.x;  // over KCLS*CCH = 76800
    if (idx >= KCLS * CCH) return;
    int k = idx / CCH;
    int c = idx - k * CCH;

    float S = 0.f;
#pragma unroll
    for (int s = 0; s < NSEG; s++) S += g_Sp[k * NSEG + s];

    float acc = 0.f;
#pragma unroll 8
    for (int pc = 0; pc < PCHUNKS; pc++)
        acc += g_part[(size_t)pc * KPAD * CCH + (size_t)k * CCH + c];

    out[idx] = acc / fmaxf(S, 1e-6f);
}

// ---------------------------------------------------------------------------
extern "C" void kernel_launch(void* const* d_in, const int* in_sizes, int n_in,
                              void* d_out, int out_size) {
    const float* feats  = (const float*)d_in[0];  // (512, 512, 512)
    const float* logits = (const float*)d_in[1];  // (150, 512, 512)
    float* out = (float*)d_out;                   // (150, 512)

    cudaFuncSetAttribute(gemm_partial,
                         cudaFuncAttributeMaxDynamicSharedMemorySize, SMEM_TOTAL);

    softmax_kernel<<<NPIX / 256, 256>>>(logits);
    colsum_kernel<<<dim3(KCLS, NSEG), 256>>>();
    gemm_partial<<<dim3(PCHUNKS, CCH / NT), 256, SMEM_TOTAL>>>(feats);
    finalize_kernel<<<(KCLS * CCH + 255) / 256, 256>>>(out);
}